// round 1
// baseline (speedup 1.0000x reference)
#include <cuda_runtime.h>
#include <math.h>

// ---------------- problem constants ----------------
#define BB   4
#define LL   1024
#define DIN  256
#define DM   512
#define HH   8
#define DV   64
#define DFF  2048
#define NLAY 2
#define DINP (2*HH*DM + HH*DV)   // 8704
#define MROWS (BB*LL)            // 4096
#define NINF (-1.0e6f)

// ---------------- scratch (__device__ globals; no allocation allowed) ------
__device__ float g_x[MROWS * DM];            // 8 MB
__device__ float g_proj[MROWS * DINP];       // ~142 MB
__device__ float g_scores[BB * HH * LL * LL];// ~134 MB
__device__ float g_sa[MROWS * (HH*DV)];      // 8 MB
__device__ float g_tmp[MROWS * DM];          // 8 MB
__device__ float g_ff[MROWS * DFF];          // 32 MB

// ---------------- generic TN SGEMM: C[M,N] = scale*(A[M,K] @ B[N,K]^T) + bias ----
// 64x64 block tile, 16 k-chunk, 256 threads, 4x4 per thread.
// Batched via blockIdx.z decomposed as (zb, zh) with independent offsets.
#define BM 64
#define BN 64
#define BK 16

__global__ void __launch_bounds__(256)
sgemm_tn(const float* __restrict__ A, int lda,
         const float* __restrict__ B, int ldb,
         float* __restrict__ C, int ldc,
         const float* __restrict__ bias,
         int K, float scale, int relu, int ZH,
         long long aob, long long aoh,
         long long bob, long long boh,
         long long cob, long long coh)
{
    int z  = blockIdx.z;
    int zb = z / ZH, zh = z % ZH;
    A += (size_t)zb * aob + (size_t)zh * aoh;
    B += (size_t)zb * bob + (size_t)zh * boh;
    C += (size_t)zb * cob + (size_t)zh * coh;

    __shared__ float As[BK][BM];
    __shared__ float Bs[BK][BN];

    int tid = threadIdx.x;
    int tx = tid % 16, ty = tid / 16;
    int m0 = blockIdx.y * BM;
    int n0 = blockIdx.x * BN;

    int lr = tid >> 2;         // 0..63
    int lk = (tid & 3) * 4;    // 0,4,8,12

    float acc[4][4] = {};

    for (int kc = 0; kc < K; kc += BK) {
        float4 a4 = *reinterpret_cast<const float4*>(A + (size_t)(m0 + lr) * lda + kc + lk);
        float4 b4 = *reinterpret_cast<const float4*>(B + (size_t)(n0 + lr) * ldb + kc + lk);
        __syncthreads();
        As[lk+0][lr] = a4.x; As[lk+1][lr] = a4.y; As[lk+2][lr] = a4.z; As[lk+3][lr] = a4.w;
        Bs[lk+0][lr] = b4.x; Bs[lk+1][lr] = b4.y; Bs[lk+2][lr] = b4.z; Bs[lk+3][lr] = b4.w;
        __syncthreads();
        #pragma unroll
        for (int k = 0; k < BK; k++) {
            float4 av = *reinterpret_cast<const float4*>(&As[k][ty * 4]);
            float4 bv = *reinterpret_cast<const float4*>(&Bs[k][tx * 4]);
            float aa[4] = {av.x, av.y, av.z, av.w};
            float bb[4] = {bv.x, bv.y, bv.z, bv.w};
            #pragma unroll
            for (int i = 0; i < 4; i++)
                #pragma unroll
                for (int j = 0; j < 4; j++)
                    acc[i][j] += aa[i] * bb[j];
        }
    }

    #pragma unroll
    for (int i = 0; i < 4; i++) {
        int m = m0 + ty * 4 + i;
        #pragma unroll
        for (int j = 0; j < 4; j++) {
            int n = n0 + tx * 4 + j;
            float v = acc[i][j] * scale;
            if (bias) v += bias[n];
            if (relu) v = fmaxf(v, 0.0f);
            C[(size_t)m * ldc + n] = v;
        }
    }
}

// ---------------- NN SGEMM: C[M,N] = A[M,K] @ B[K,N] (B row-major) -------------
__global__ void __launch_bounds__(256)
sgemm_nn(const float* __restrict__ A, int lda,
         const float* __restrict__ B, int ldb,
         float* __restrict__ C, int ldc,
         int K, int ZH,
         long long aob, long long aoh,
         long long bob, long long boh,
         long long cob, long long coh)
{
    int z  = blockIdx.z;
    int zb = z / ZH, zh = z % ZH;
    A += (size_t)zb * aob + (size_t)zh * aoh;
    B += (size_t)zb * bob + (size_t)zh * boh;
    C += (size_t)zb * cob + (size_t)zh * coh;

    __shared__ float As[BK][BM];
    __shared__ float Bs[BK][BN];

    int tid = threadIdx.x;
    int tx = tid % 16, ty = tid / 16;
    int m0 = blockIdx.y * BM;
    int n0 = blockIdx.x * BN;

    int lr = tid >> 2;          // A: row in tile
    int lk = (tid & 3) * 4;     // A: k offset
    int kr = tid >> 4;          // B: k row (0..15)
    int ng = (tid & 15) * 4;    // B: n offset

    float acc[4][4] = {};

    for (int kc = 0; kc < K; kc += BK) {
        float4 a4 = *reinterpret_cast<const float4*>(A + (size_t)(m0 + lr) * lda + kc + lk);
        float4 b4 = *reinterpret_cast<const float4*>(B + (size_t)(kc + kr) * ldb + n0 + ng);
        __syncthreads();
        As[lk+0][lr] = a4.x; As[lk+1][lr] = a4.y; As[lk+2][lr] = a4.z; As[lk+3][lr] = a4.w;
        *reinterpret_cast<float4*>(&Bs[kr][ng]) = b4;
        __syncthreads();
        #pragma unroll
        for (int k = 0; k < BK; k++) {
            float4 av = *reinterpret_cast<const float4*>(&As[k][ty * 4]);
            float4 bv = *reinterpret_cast<const float4*>(&Bs[k][tx * 4]);
            float aa[4] = {av.x, av.y, av.z, av.w};
            float bb[4] = {bv.x, bv.y, bv.z, bv.w};
            #pragma unroll
            for (int i = 0; i < 4; i++)
                #pragma unroll
                for (int j = 0; j < 4; j++)
                    acc[i][j] += aa[i] * bb[j];
        }
    }

    #pragma unroll
    for (int i = 0; i < 4; i++) {
        int m = m0 + ty * 4 + i;
        #pragma unroll
        for (int j = 0; j < 4; j++) {
            int n = n0 + tx * 4 + j;
            C[(size_t)m * ldc + n] = acc[i][j];
        }
    }
}

// ---------------- masked softmax over rows of length L --------------------
// row = (b*H + h)*L + l ; masked cols: m >= seq_len[b] OR l <= m  -> NINF
__global__ void __launch_bounds__(256)
softmax_kernel(float* __restrict__ w, const int* __restrict__ seq_lens)
{
    __shared__ float red[256];
    int row = blockIdx.x;
    int l = row % LL;
    int b = row / (HH * LL);
    float* p = w + (size_t)row * LL;
    int sl = seq_lens[b];
    int tid = threadIdx.x;

    float v[4];
    float mx = -3.4e38f;
    #pragma unroll
    for (int i = 0; i < 4; i++) {
        int m = tid + i * 256;
        float x = p[m];
        if (m >= sl || l <= m) x = NINF;
        v[i] = x;
        mx = fmaxf(mx, x);
    }
    red[tid] = mx; __syncthreads();
    for (int o = 128; o > 0; o >>= 1) {
        if (tid < o) red[tid] = fmaxf(red[tid], red[tid + o]);
        __syncthreads();
    }
    mx = red[0];
    __syncthreads();

    float sum = 0.0f;
    #pragma unroll
    for (int i = 0; i < 4; i++) { v[i] = __expf(v[i] - mx); sum += v[i]; }
    red[tid] = sum; __syncthreads();
    for (int o = 128; o > 0; o >>= 1) {
        if (tid < o) red[tid] += red[tid + o];
        __syncthreads();
    }
    float inv = 1.0f / red[0];
    #pragma unroll
    for (int i = 0; i < 4; i++) p[tid + i * 256] = v[i] * inv;
}

// ---------------- residual + LayerNorm (row = b*L + l, width DM) ----------
__global__ void __launch_bounds__(128)
ln_kernel(const float* __restrict__ x, const float* __restrict__ r,
          const float* __restrict__ g, const float* __restrict__ be,
          float* __restrict__ out, int zero_l0)
{
    __shared__ float red[128];
    int row = blockIdx.x;
    int l = row % LL;
    const float* xp = x + (size_t)row * DM;
    const float* rp = r + (size_t)row * DM;
    int tid = threadIdx.x;
    bool skip = (zero_l0 && l == 0);

    float v[4];
    float s = 0.0f;
    #pragma unroll
    for (int i = 0; i < 4; i++) {
        int c = tid + i * 128;
        v[i] = xp[c] + (skip ? 0.0f : rp[c]);
        s += v[i];
    }
    red[tid] = s; __syncthreads();
    for (int o = 64; o > 0; o >>= 1) {
        if (tid < o) red[tid] += red[tid + o];
        __syncthreads();
    }
    float mu = red[0] * (1.0f / DM);
    __syncthreads();

    float vs = 0.0f;
    #pragma unroll
    for (int i = 0; i < 4; i++) { float d = v[i] - mu; vs += d * d; }
    red[tid] = vs; __syncthreads();
    for (int o = 64; o > 0; o >>= 1) {
        if (tid < o) red[tid] += red[tid + o];
        __syncthreads();
    }
    float inv = rsqrtf(red[0] * (1.0f / DM) + 1e-5f);
    #pragma unroll
    for (int i = 0; i < 4; i++) {
        int c = tid + i * 128;
        out[(size_t)row * DM + c] = (v[i] - mu) * inv * g[c] + be[c];
    }
}

// ---------------- positional encoding add ---------------------------------
__global__ void __launch_bounds__(256)
add_pos_kernel(float* __restrict__ x, const float* __restrict__ times)
{
    int idx = blockIdx.x * blockDim.x + threadIdx.x;
    if (idx >= MROWS * DM) return;
    int j = idx % DM;
    int row = idx / DM;
    float t = times[row];
    int jj = (j < DM / 2) ? j : j - DM / 2;
    float d = (float)jj / (float)(DM / 2 - 1);
    float denum = powf(10000.0f, d);   // POS_M_LO * (5*POS_M_HI/POS_M_LO)^d
    float arg = t / denum;
    x[idx] += (j < DM / 2) ? sinf(arg) : cosf(arg);
}

// ---------------- host-side orchestration ----------------------------------
extern "C" void kernel_launch(void* const* d_in, const int* in_sizes, int n_in,
                              void* d_out, int out_size)
{
    const float* emb   = (const float*)d_in[0];
    const float* times = (const float*)d_in[1];
    const int*   seq   = (const int*)  d_in[2];
    const float* Wp    = (const float*)d_in[3];
    const float* bp    = (const float*)d_in[4];
    const float* Win   = (const float*)d_in[5];
    const float* bin_  = (const float*)d_in[6];
    const float* Wout  = (const float*)d_in[7];
    const float* bout  = (const float*)d_in[8];
    const float* g1    = (const float*)d_in[9];
    const float* be1   = (const float*)d_in[10];
    const float* W1    = (const float*)d_in[11];
    const float* b1    = (const float*)d_in[12];
    const float* W2    = (const float*)d_in[13];
    const float* b2    = (const float*)d_in[14];
    const float* g2    = (const float*)d_in[15];
    const float* be2   = (const float*)d_in[16];

    float* x      = nullptr;
    float* proj   = nullptr;
    float* scores = nullptr;
    float* sa     = nullptr;
    float* tmp    = nullptr;
    float* ff     = nullptr;
    cudaGetSymbolAddress((void**)&x,      g_x);
    cudaGetSymbolAddress((void**)&proj,   g_proj);
    cudaGetSymbolAddress((void**)&scores, g_scores);
    cudaGetSymbolAddress((void**)&sa,     g_sa);
    cudaGetSymbolAddress((void**)&tmp,    g_tmp);
    cudaGetSymbolAddress((void**)&ff,     g_ff);

    const float inv_sqrt_d = 1.0f / sqrtf((float)DM);

    // x = emb @ Wp^T + bp
    sgemm_tn<<<dim3(DM / BN, MROWS / BM, 1), 256>>>(
        emb, DIN, Wp, DIN, x, DM, bp, DIN, 1.0f, 0, 1, 0, 0, 0, 0, 0, 0);
    // x += pos_encode(times)
    add_pos_kernel<<<(MROWS * DM + 255) / 256, 256>>>(x, times);

    for (int i = 0; i < NLAY; i++) {
        const float* Wi   = Win  + (size_t)i * DINP * DM;
        const float* bini = bin_ + (size_t)i * DINP;
        const float* Woi  = Wout + (size_t)i * DM * (HH * DV);
        const float* boi  = bout + (size_t)i * DM;
        const float* g1i  = g1   + (size_t)i * DM;
        const float* be1i = be1  + (size_t)i * DM;
        const float* W1i  = W1   + (size_t)i * DFF * DM;
        const float* b1i  = b1   + (size_t)i * DFF;
        const float* W2i  = W2   + (size_t)i * DM * DFF;
        const float* b2i  = b2   + (size_t)i * DM;
        const float* g2i  = g2   + (size_t)i * DM;
        const float* be2i = be2  + (size_t)i * DM;

        // proj = x @ Win^T + bin   (4096 x 8704, K=512)
        sgemm_tn<<<dim3(DINP / BN, MROWS / BM, 1), 256>>>(
            x, DM, Wi, DM, proj, DINP, bini, DM, 1.0f, 0, 1, 0, 0, 0, 0, 0, 0);

        // scores[b,h] = q[b,:,h,:] @ k[b,:,h,:]^T * 1/sqrt(512)
        sgemm_tn<<<dim3(LL / BN, LL / BM, BB * HH), 256>>>(
            proj, DINP,                  // q base: col h*DM
            proj + HH * DM, DINP,        // k base: col 4096 + h*DM
            scores, LL, nullptr, DM, inv_sqrt_d, 0, HH,
            (long long)LL * DINP, (long long)DM,
            (long long)LL * DINP, (long long)DM,
            (long long)HH * LL * LL, (long long)LL * LL);

        // masked softmax over key dim
        softmax_kernel<<<BB * HH * LL, 256>>>(scores, seq);

        // sa[b,l,h,:] = scores[b,h] @ v[b,:,h,:]   (NN, N=64, K=1024)
        sgemm_nn<<<dim3(DV / BN, LL / BM, BB * HH), 256>>>(
            scores, LL,
            proj + 2 * HH * DM, DINP,    // v base: col 8192 + h*DV
            sa, HH * DV, LL, HH,
            (long long)HH * LL * LL, (long long)LL * LL,
            (long long)LL * DINP, (long long)DV,
            (long long)LL * (HH * DV), (long long)DV);

        // tmp = sa @ Wout^T + bout   (4096 x 512, K=512)
        sgemm_tn<<<dim3(DM / BN, MROWS / BM, 1), 256>>>(
            sa, HH * DV, Woi, HH * DV, tmp, DM, boi, HH * DV, 1.0f, 0, 1,
            0, 0, 0, 0, 0, 0);

        // x = LN(x + tmp) with row l==0 zeroed residual
        ln_kernel<<<MROWS, 128>>>(x, tmp, g1i, be1i, x, 1);

        // ff = relu(x @ W1^T + b1)   (4096 x 2048, K=512)
        sgemm_tn<<<dim3(DFF / BN, MROWS / BM, 1), 256>>>(
            x, DM, W1i, DM, ff, DFF, b1i, DM, 1.0f, 1, 1, 0, 0, 0, 0, 0, 0);

        // tmp = ff @ W2^T + b2   (4096 x 512, K=2048)
        sgemm_tn<<<dim3(DM / BN, MROWS / BM, 1), 256>>>(
            ff, DFF, W2i, DFF, tmp, DM, b2i, DFF, 1.0f, 0, 1, 0, 0, 0, 0, 0, 0);

        // x = LN(x + tmp); last layer writes straight to d_out
        float* dst = (i == NLAY - 1) ? (float*)d_out : x;
        ln_kernel<<<MROWS, 128>>>(x, tmp, g2i, be2i, dst, 0);
    }
}

// round 2
// speedup vs baseline: 3.8349x; 3.8349x over previous
#include <cuda_runtime.h>
#include <math.h>
#include <stdint.h>

// ---------------- problem constants ----------------
#define BB   4
#define LL   1024
#define DIN  256
#define DM   512
#define HH   8
#define DV   64
#define DFF  2048
#define NLAY 2
#define DINP (2*HH*DM + HH*DV)   // 8704
#define MROWS (BB*LL)            // 4096
#define NINF (-1.0e6f)

#define BKP 36   // padded k stride (32 + 4) -> conflict-free fragment LDS

// ---------------- scratch (__device__ globals; no allocation allowed) ------
__device__ float g_x[MROWS * DM];
__device__ float g_proj[MROWS * DINP];
__device__ float g_scores[BB * HH * LL * LL];
__device__ float g_sa[MROWS * (HH*DV)];
__device__ float g_tmp[MROWS * DM];
__device__ float g_ff[MROWS * DFF];

// ---------------- tf32 helpers ----------------
__device__ __forceinline__ uint32_t f2tf(float f) {
    uint32_t r; asm("cvt.rna.tf32.f32 %0, %1;" : "=r"(r) : "f"(f)); return r;
}
__device__ __forceinline__ void mma_tf32(float* c, const uint32_t* a, const uint32_t* b) {
    asm volatile("mma.sync.aligned.m16n8k8.row.col.f32.tf32.tf32.f32 "
        "{%0,%1,%2,%3}, {%4,%5,%6,%7}, {%8,%9}, {%0,%1,%2,%3};"
        : "+f"(c[0]), "+f"(c[1]), "+f"(c[2]), "+f"(c[3])
        : "r"(a[0]), "r"(a[1]), "r"(a[2]), "r"(a[3]), "r"(b[0]), "r"(b[1]));
}

// ============================================================================
// TN tensor GEMM: C[M,N] = scale*(A[M,K] @ B[N,K]^T) + bias, optional relu.
// BM=BN=128, BK=32, 256 threads (8 warps, 2m x 4n), warp tile 64x32.
// TRI=1: lower-triangular 128x128 tile set for strictly-causal scores.
// ============================================================================
template<int TRI>
__global__ void __launch_bounds__(256)
tgemm_tn(const float* __restrict__ A, int lda,
         const float* __restrict__ B, int ldb,
         float* __restrict__ C, int ldc,
         const float* __restrict__ bias,
         int K, float scale, int relu, int ZH,
         long long aob, long long aoh,
         long long bob, long long boh,
         long long cob, long long coh)
{
    const int BM = 128, BN = 128, BK = 32;
    extern __shared__ uint32_t sm[];
    uint32_t (*As)[BM][BKP] = (uint32_t(*)[BM][BKP])sm;
    uint32_t (*Bs)[BN][BKP] = (uint32_t(*)[BN][BKP])(sm + 2 * BM * BKP);

    int z = blockIdx.z, zb = z / ZH, zh = z % ZH;
    A += (size_t)zb * aob + (size_t)zh * aoh;
    B += (size_t)zb * bob + (size_t)zh * boh;
    C += (size_t)zb * cob + (size_t)zh * coh;

    int m0, n0;
    if (TRI) {
        int id = blockIdx.x;
        int ti = (int)((sqrtf(8.0f * id + 1.0f) - 1.0f) * 0.5f);
        while ((ti + 1) * (ti + 2) / 2 <= id) ti++;
        while (ti * (ti + 1) / 2 > id) ti--;
        int tj = id - ti * (ti + 1) / 2;
        m0 = ti * BM; n0 = tj * BN;
    } else {
        m0 = blockIdx.y * BM; n0 = blockIdx.x * BN;
    }

    int tid = threadIdx.x;
    int warp = tid >> 5, lane = tid & 31;
    int wm0 = (warp >> 2) * 64;
    int wn0 = (warp & 3) * 32;
    int r = lane >> 2, cq = lane & 3;

    int lrow = tid >> 3;          // staging row 0..31 per pass
    int lcol = (tid & 7) * 4;     // staging col (floats)

    float acc[4][4][4] = {};
    float4 ra[4], rb[4];

    // prologue: load k-tile 0, fill buffer 0
    #pragma unroll
    for (int p = 0; p < 4; p++) {
        ra[p] = *(const float4*)(A + (size_t)(m0 + p * 32 + lrow) * lda + lcol);
        rb[p] = *(const float4*)(B + (size_t)(n0 + p * 32 + lrow) * ldb + lcol);
    }
    #pragma unroll
    for (int p = 0; p < 4; p++) {
        uint32_t* as = &As[0][p * 32 + lrow][lcol];
        as[0] = f2tf(ra[p].x); as[1] = f2tf(ra[p].y); as[2] = f2tf(ra[p].z); as[3] = f2tf(ra[p].w);
        uint32_t* bs = &Bs[0][p * 32 + lrow][lcol];
        bs[0] = f2tf(rb[p].x); bs[1] = f2tf(rb[p].y); bs[2] = f2tf(rb[p].z); bs[3] = f2tf(rb[p].w);
    }
    __syncthreads();

    int KT = K / BK;
    for (int kt = 0; kt < KT; kt++) {
        int cur = kt & 1, nxt = cur ^ 1;
        if (kt + 1 < KT) {
            int kc = (kt + 1) * BK;
            #pragma unroll
            for (int p = 0; p < 4; p++) {
                ra[p] = *(const float4*)(A + (size_t)(m0 + p * 32 + lrow) * lda + kc + lcol);
                rb[p] = *(const float4*)(B + (size_t)(n0 + p * 32 + lrow) * ldb + kc + lcol);
            }
        }
        #pragma unroll
        for (int ks = 0; ks < 32; ks += 8) {
            uint32_t a[4][4], b[4][2];
            #pragma unroll
            for (int mf = 0; mf < 4; mf++) {
                int row = wm0 + mf * 16 + r;
                a[mf][0] = As[cur][row][ks + cq];
                a[mf][1] = As[cur][row + 8][ks + cq];
                a[mf][2] = As[cur][row][ks + cq + 4];
                a[mf][3] = As[cur][row + 8][ks + cq + 4];
            }
            #pragma unroll
            for (int nf = 0; nf < 4; nf++) {
                int col = wn0 + nf * 8 + r;
                b[nf][0] = Bs[cur][col][ks + cq];
                b[nf][1] = Bs[cur][col][ks + cq + 4];
            }
            #pragma unroll
            for (int mf = 0; mf < 4; mf++)
                #pragma unroll
                for (int nf = 0; nf < 4; nf++)
                    mma_tf32(acc[mf][nf], a[mf], b[nf]);
        }
        if (kt + 1 < KT) {
            #pragma unroll
            for (int p = 0; p < 4; p++) {
                uint32_t* as = &As[nxt][p * 32 + lrow][lcol];
                as[0] = f2tf(ra[p].x); as[1] = f2tf(ra[p].y); as[2] = f2tf(ra[p].z); as[3] = f2tf(ra[p].w);
                uint32_t* bs = &Bs[nxt][p * 32 + lrow][lcol];
                bs[0] = f2tf(rb[p].x); bs[1] = f2tf(rb[p].y); bs[2] = f2tf(rb[p].z); bs[3] = f2tf(rb[p].w);
            }
            __syncthreads();
        }
    }

    // epilogue
    #pragma unroll
    for (int mf = 0; mf < 4; mf++) {
        #pragma unroll
        for (int nf = 0; nf < 4; nf++) {
            int m = m0 + wm0 + mf * 16 + r;
            int n = n0 + wn0 + nf * 8 + cq * 2;
            float v0 = acc[mf][nf][0] * scale;
            float v1 = acc[mf][nf][1] * scale;
            float v2 = acc[mf][nf][2] * scale;
            float v3 = acc[mf][nf][3] * scale;
            if (bias) { float b0 = bias[n], b1 = bias[n + 1]; v0 += b0; v1 += b1; v2 += b0; v3 += b1; }
            if (relu) { v0 = fmaxf(v0, 0.f); v1 = fmaxf(v1, 0.f); v2 = fmaxf(v2, 0.f); v3 = fmaxf(v3, 0.f); }
            *(float2*)&C[(size_t)m * ldc + n] = make_float2(v0, v1);
            *(float2*)&C[(size_t)(m + 8) * ldc + n] = make_float2(v2, v3);
        }
    }
}

// ============================================================================
// NN tensor GEMM for AV: C[M,N] = A[M,K] @ B[K,N] (B row-major, transposed in
// smem). BM=128, BN=64, BK=32, 256 threads (8 warps, 4m x 2n), warp 32x32.
// Causal k-limit: weights are zero for k >= m0+BM (softmax wrote exact zeros).
// ============================================================================
__global__ void __launch_bounds__(256)
tgemm_nn_av(const float* __restrict__ A, int lda,
            const float* __restrict__ B, int ldb,
            float* __restrict__ C, int ldc,
            int K, int ZH,
            long long aob, long long aoh,
            long long bob, long long boh,
            long long cob, long long coh)
{
    const int BM = 128, BN = 64, BK = 32;
    extern __shared__ uint32_t sm[];
    uint32_t (*As)[BM][BKP] = (uint32_t(*)[BM][BKP])sm;
    uint32_t (*Bs)[BN][BKP] = (uint32_t(*)[BN][BKP])(sm + 2 * BM * BKP);

    int z = blockIdx.z, zb = z / ZH, zh = z % ZH;
    A += (size_t)zb * aob + (size_t)zh * aoh;
    B += (size_t)zb * bob + (size_t)zh * boh;
    C += (size_t)zb * cob + (size_t)zh * coh;

    int m0 = blockIdx.y * BM;
    int n0 = blockIdx.x * BN;
    int Keff = min(K, m0 + BM);      // causal: later keys have zero weight

    int tid = threadIdx.x;
    int warp = tid >> 5, lane = tid & 31;
    int wm0 = (warp >> 1) * 32;
    int wn0 = (warp & 1) * 32;
    int r = lane >> 2, cq = lane & 3;

    int lrow = tid >> 3;          // A staging
    int lcol = (tid & 7) * 4;
    int bkrow0 = tid >> 4;        // B staging: k row (0..15 per pass)
    int bnc = (tid & 15) * 4;     // B staging: n col

    float acc[2][4][4] = {};
    float4 ra[4], rb[2];

    #pragma unroll
    for (int p = 0; p < 4; p++)
        ra[p] = *(const float4*)(A + (size_t)(m0 + p * 32 + lrow) * lda + lcol);
    #pragma unroll
    for (int p = 0; p < 2; p++)
        rb[p] = *(const float4*)(B + (size_t)(p * 16 + bkrow0) * ldb + n0 + bnc);
    #pragma unroll
    for (int p = 0; p < 4; p++) {
        uint32_t* as = &As[0][p * 32 + lrow][lcol];
        as[0] = f2tf(ra[p].x); as[1] = f2tf(ra[p].y); as[2] = f2tf(ra[p].z); as[3] = f2tf(ra[p].w);
    }
    #pragma unroll
    for (int p = 0; p < 2; p++) {
        int kr = p * 16 + bkrow0;
        Bs[0][bnc + 0][kr] = f2tf(rb[p].x);
        Bs[0][bnc + 1][kr] = f2tf(rb[p].y);
        Bs[0][bnc + 2][kr] = f2tf(rb[p].z);
        Bs[0][bnc + 3][kr] = f2tf(rb[p].w);
    }
    __syncthreads();

    int KT = Keff / BK;
    for (int kt = 0; kt < KT; kt++) {
        int cur = kt & 1, nxt = cur ^ 1;
        if (kt + 1 < KT) {
            int kc = (kt + 1) * BK;
            #pragma unroll
            for (int p = 0; p < 4; p++)
                ra[p] = *(const float4*)(A + (size_t)(m0 + p * 32 + lrow) * lda + kc + lcol);
            #pragma unroll
            for (int p = 0; p < 2; p++)
                rb[p] = *(const float4*)(B + (size_t)(kc + p * 16 + bkrow0) * ldb + n0 + bnc);
        }
        #pragma unroll
        for (int ks = 0; ks < 32; ks += 8) {
            uint32_t a[2][4], b[4][2];
            #pragma unroll
            for (int mf = 0; mf < 2; mf++) {
                int row = wm0 + mf * 16 + r;
                a[mf][0] = As[cur][row][ks + cq];
                a[mf][1] = As[cur][row + 8][ks + cq];
                a[mf][2] = As[cur][row][ks + cq + 4];
                a[mf][3] = As[cur][row + 8][ks + cq + 4];
            }
            #pragma unroll
            for (int nf = 0; nf < 4; nf++) {
                int col = wn0 + nf * 8 + r;
                b[nf][0] = Bs[cur][col][ks + cq];
                b[nf][1] = Bs[cur][col][ks + cq + 4];
            }
            #pragma unroll
            for (int mf = 0; mf < 2; mf++)
                #pragma unroll
                for (int nf = 0; nf < 4; nf++)
                    mma_tf32(acc[mf][nf], a[mf], b[nf]);
        }
        if (kt + 1 < KT) {
            #pragma unroll
            for (int p = 0; p < 4; p++) {
                uint32_t* as = &As[nxt][p * 32 + lrow][lcol];
                as[0] = f2tf(ra[p].x); as[1] = f2tf(ra[p].y); as[2] = f2tf(ra[p].z); as[3] = f2tf(ra[p].w);
            }
            #pragma unroll
            for (int p = 0; p < 2; p++) {
                int kr = p * 16 + bkrow0;
                Bs[nxt][bnc + 0][kr] = f2tf(rb[p].x);
                Bs[nxt][bnc + 1][kr] = f2tf(rb[p].y);
                Bs[nxt][bnc + 2][kr] = f2tf(rb[p].z);
                Bs[nxt][bnc + 3][kr] = f2tf(rb[p].w);
            }
            __syncthreads();
        }
    }

    #pragma unroll
    for (int mf = 0; mf < 2; mf++) {
        #pragma unroll
        for (int nf = 0; nf < 4; nf++) {
            int m = m0 + wm0 + mf * 16 + r;
            int n = n0 + wn0 + nf * 8 + cq * 2;
            *(float2*)&C[(size_t)m * ldc + n] = make_float2(acc[mf][nf][0], acc[mf][nf][1]);
            *(float2*)&C[(size_t)(m + 8) * ldc + n] = make_float2(acc[mf][nf][2], acc[mf][nf][3]);
        }
    }
}

// ---------------- masked softmax over rows of length L --------------------
__global__ void __launch_bounds__(256)
softmax_kernel(float* __restrict__ w, const int* __restrict__ seq_lens)
{
    __shared__ float red[256];
    int row = blockIdx.x;
    int l = row % LL;
    int b = row / (HH * LL);
    float* p = w + (size_t)row * LL;
    int sl = seq_lens[b];
    int tid = threadIdx.x;

    float v[4];
    float mx = -3.4e38f;
    #pragma unroll
    for (int i = 0; i < 4; i++) {
        int m = tid + i * 256;
        float x = (m < sl && m < l) ? p[m] : NINF;   // skip loading masked region
        v[i] = x;
        mx = fmaxf(mx, x);
    }
    red[tid] = mx; __syncthreads();
    for (int o = 128; o > 0; o >>= 1) {
        if (tid < o) red[tid] = fmaxf(red[tid], red[tid + o]);
        __syncthreads();
    }
    mx = red[0];
    __syncthreads();

    float sum = 0.0f;
    #pragma unroll
    for (int i = 0; i < 4; i++) { v[i] = __expf(v[i] - mx); sum += v[i]; }
    red[tid] = sum; __syncthreads();
    for (int o = 128; o > 0; o >>= 1) {
        if (tid < o) red[tid] += red[tid + o];
        __syncthreads();
    }
    float inv = 1.0f / red[0];
    #pragma unroll
    for (int i = 0; i < 4; i++) p[tid + i * 256] = v[i] * inv;
}

// ---------------- residual + LayerNorm -------------------------------------
__global__ void __launch_bounds__(128)
ln_kernel(const float* __restrict__ x, const float* __restrict__ r,
          const float* __restrict__ g, const float* __restrict__ be,
          float* __restrict__ out, int zero_l0)
{
    __shared__ float red[128];
    int row = blockIdx.x;
    int l = row % LL;
    const float* xp = x + (size_t)row * DM;
    const float* rp = r + (size_t)row * DM;
    int tid = threadIdx.x;
    bool skip = (zero_l0 && l == 0);

    float v[4];
    float s = 0.0f;
    #pragma unroll
    for (int i = 0; i < 4; i++) {
        int c = tid + i * 128;
        v[i] = xp[c] + (skip ? 0.0f : rp[c]);
        s += v[i];
    }
    red[tid] = s; __syncthreads();
    for (int o = 64; o > 0; o >>= 1) {
        if (tid < o) red[tid] += red[tid + o];
        __syncthreads();
    }
    float mu = red[0] * (1.0f / DM);
    __syncthreads();

    float vs = 0.0f;
    #pragma unroll
    for (int i = 0; i < 4; i++) { float d = v[i] - mu; vs += d * d; }
    red[tid] = vs; __syncthreads();
    for (int o = 64; o > 0; o >>= 1) {
        if (tid < o) red[tid] += red[tid + o];
        __syncthreads();
    }
    float inv = rsqrtf(red[0] * (1.0f / DM) + 1e-5f);
    #pragma unroll
    for (int i = 0; i < 4; i++) {
        int c = tid + i * 128;
        out[(size_t)row * DM + c] = (v[i] - mu) * inv * g[c] + be[c];
    }
}

// ---------------- positional encoding add ---------------------------------
__global__ void __launch_bounds__(256)
add_pos_kernel(float* __restrict__ x, const float* __restrict__ times)
{
    int idx = blockIdx.x * blockDim.x + threadIdx.x;
    if (idx >= MROWS * DM) return;
    int j = idx % DM;
    int row = idx / DM;
    float t = times[row];
    int jj = (j < DM / 2) ? j : j - DM / 2;
    float d = (float)jj / (float)(DM / 2 - 1);
    float denum = powf(10000.0f, d);
    float arg = t / denum;
    x[idx] += (j < DM / 2) ? sinf(arg) : cosf(arg);
}

// ---------------- host-side orchestration ----------------------------------
extern "C" void kernel_launch(void* const* d_in, const int* in_sizes, int n_in,
                              void* d_out, int out_size)
{
    const float* emb   = (const float*)d_in[0];
    const float* times = (const float*)d_in[1];
    const int*   seq   = (const int*)  d_in[2];
    const float* Wp    = (const float*)d_in[3];
    const float* bp    = (const float*)d_in[4];
    const float* Win   = (const float*)d_in[5];
    const float* bin_  = (const float*)d_in[6];
    const float* Wout  = (const float*)d_in[7];
    const float* bout  = (const float*)d_in[8];
    const float* g1    = (const float*)d_in[9];
    const float* be1   = (const float*)d_in[10];
    const float* W1    = (const float*)d_in[11];
    const float* b1    = (const float*)d_in[12];
    const float* W2    = (const float*)d_in[13];
    const float* b2    = (const float*)d_in[14];
    const float* g2    = (const float*)d_in[15];
    const float* be2   = (const float*)d_in[16];

    float *x, *proj, *scores, *sa, *tmp, *ff;
    cudaGetSymbolAddress((void**)&x,      g_x);
    cudaGetSymbolAddress((void**)&proj,   g_proj);
    cudaGetSymbolAddress((void**)&scores, g_scores);
    cudaGetSymbolAddress((void**)&sa,     g_sa);
    cudaGetSymbolAddress((void**)&tmp,    g_tmp);
    cudaGetSymbolAddress((void**)&ff,     g_ff);

    const int SMEM_TN = (2 * 128 * BKP + 2 * 128 * BKP) * 4;   // 73728
    const int SMEM_NN = (2 * 128 * BKP + 2 * 64 * BKP) * 4;    // 55296
    cudaFuncSetAttribute(tgemm_tn<0>, cudaFuncAttributeMaxDynamicSharedMemorySize, SMEM_TN);
    cudaFuncSetAttribute(tgemm_tn<1>, cudaFuncAttributeMaxDynamicSharedMemorySize, SMEM_TN);
    cudaFuncSetAttribute(tgemm_nn_av, cudaFuncAttributeMaxDynamicSharedMemorySize, SMEM_NN);

    const float inv_sqrt_d = 1.0f / sqrtf((float)DM);

    // x = emb @ Wp^T + bp
    tgemm_tn<0><<<dim3(DM / 128, MROWS / 128, 1), 256, SMEM_TN>>>(
        emb, DIN, Wp, DIN, x, DM, bp, DIN, 1.0f, 0, 1, 0, 0, 0, 0, 0, 0);
    add_pos_kernel<<<(MROWS * DM + 255) / 256, 256>>>(x, times);

    for (int i = 0; i < NLAY; i++) {
        const float* Wi   = Win  + (size_t)i * DINP * DM;
        const float* bini = bin_ + (size_t)i * DINP;
        const float* Woi  = Wout + (size_t)i * DM * (HH * DV);
        const float* boi  = bout + (size_t)i * DM;
        const float* g1i  = g1   + (size_t)i * DM;
        const float* be1i = be1  + (size_t)i * DM;
        const float* W1i  = W1   + (size_t)i * DFF * DM;
        const float* b1i  = b1   + (size_t)i * DFF;
        const float* W2i  = W2   + (size_t)i * DM * DFF;
        const float* b2i  = b2   + (size_t)i * DM;
        const float* g2i  = g2   + (size_t)i * DM;
        const float* be2i = be2  + (size_t)i * DM;

        // proj = x @ Win^T + bin   (4096 x 8704, K=512)
        tgemm_tn<0><<<dim3(DINP / 128, MROWS / 128, 1), 256, SMEM_TN>>>(
            x, DM, Wi, DM, proj, DINP, bini, DM, 1.0f, 0, 1, 0, 0, 0, 0, 0, 0);

        // scores: only lower-triangular tiles (36 of 64), per (b,h)
        tgemm_tn<1><<<dim3(36, 1, BB * HH), 256, SMEM_TN>>>(
            proj, DINP, proj + HH * DM, DINP, scores, LL, nullptr,
            DM, inv_sqrt_d, 0, HH,
            (long long)LL * DINP, (long long)DM,
            (long long)LL * DINP, (long long)DM,
            (long long)HH * LL * LL, (long long)LL * LL);

        // masked softmax (sanitizes skipped tiles: writes exact zeros there)
        softmax_kernel<<<BB * HH * LL, 256>>>(scores, seq);

        // sa = softmax(w) @ v  (K limited to m0+128 by causality)
        tgemm_nn_av<<<dim3(1, LL / 128, BB * HH), 256, SMEM_NN>>>(
            scores, LL, proj + 2 * HH * DM, DINP, sa, HH * DV, LL, HH,
            (long long)HH * LL * LL, (long long)LL * LL,
            (long long)LL * DINP, (long long)DV,
            (long long)LL * (HH * DV), (long long)DV);

        // tmp = sa @ Wout^T + bout
        tgemm_tn<0><<<dim3(DM / 128, MROWS / 128, 1), 256, SMEM_TN>>>(
            sa, HH * DV, Woi, HH * DV, tmp, DM, boi, HH * DV, 1.0f, 0, 1,
            0, 0, 0, 0, 0, 0);

        ln_kernel<<<MROWS, 128>>>(x, tmp, g1i, be1i, x, 1);

        // ff = relu(x @ W1^T + b1)
        tgemm_tn<0><<<dim3(DFF / 128, MROWS / 128, 1), 256, SMEM_TN>>>(
            x, DM, W1i, DM, ff, DFF, b1i, DM, 1.0f, 1, 1, 0, 0, 0, 0, 0, 0);

        // tmp = ff @ W2^T + b2
        tgemm_tn<0><<<dim3(DM / 128, MROWS / 128, 1), 256, SMEM_TN>>>(
            ff, DFF, W2i, DFF, tmp, DM, b2i, DFF, 1.0f, 0, 1, 0, 0, 0, 0, 0, 0);

        float* dst = (i == NLAY - 1) ? (float*)d_out : x;
        ln_kernel<<<MROWS, 128>>>(x, tmp, g2i, be2i, dst, 0);
    }
}

// round 3
// speedup vs baseline: 3.8428x; 1.0021x over previous
#include <cuda_runtime.h>
#include <math.h>
#include <stdint.h>

// ---------------- problem constants ----------------
#define BB   4
#define LL   1024
#define DIN  256
#define DM   512
#define HH   8
#define DV   64
#define DFF  2048
#define NLAY 2
#define DINP (2*HH*DM + HH*DV)   // 8704
#define MROWS (BB*LL)            // 4096
#define NINF (-1.0e6f)

#define BKP 36   // padded k stride (32 + 4) -> conflict-free fragment LDS

// ---------------- scratch (__device__ globals; no allocation allowed) ------
__device__ float g_x[MROWS * DM];
__device__ float g_proj[MROWS * DINP];
__device__ float g_scores[BB * HH * LL * LL];
__device__ float g_sa[MROWS * (HH*DV)];
__device__ float g_tmp[MROWS * DM];
__device__ float g_ff[MROWS * DFF];

// ---------------- tf32 helpers ----------------
__device__ __forceinline__ uint32_t f2tf(float f) {
    uint32_t r; asm("cvt.rna.tf32.f32 %0, %1;" : "=r"(r) : "f"(f)); return r;
}
__device__ __forceinline__ void mma_tf32(float* c, const uint32_t* a, const uint32_t* b) {
    asm volatile("mma.sync.aligned.m16n8k8.row.col.f32.tf32.tf32.f32 "
        "{%0,%1,%2,%3}, {%4,%5,%6,%7}, {%8,%9}, {%0,%1,%2,%3};"
        : "+f"(c[0]), "+f"(c[1]), "+f"(c[2]), "+f"(c[3])
        : "r"(a[0]), "r"(a[1]), "r"(a[2]), "r"(a[3]), "r"(b[0]), "r"(b[1]));
}

// ============================================================================
// TN tensor GEMM: C[M,N] = scale*(A[M,K] @ B[N,K]^T) + bias, optional relu.
// BM=BN=128, BK=32, 256 threads (8 warps, 2m x 4n), warp tile 64x32.
// TRI=1: lower-triangular 128x128 tile set for strictly-causal scores.
// ============================================================================
template<int TRI>
__global__ void __launch_bounds__(256)
tgemm_tn(const float* __restrict__ A, int lda,
         const float* __restrict__ B, int ldb,
         float* __restrict__ C, int ldc,
         const float* __restrict__ bias,
         int K, float scale, int relu, int ZH,
         long long aob, long long aoh,
         long long bob, long long boh,
         long long cob, long long coh)
{
    const int BM = 128, BN = 128, BK = 32;
    extern __shared__ uint32_t sm[];
    uint32_t (*As)[BM][BKP] = (uint32_t(*)[BM][BKP])sm;
    uint32_t (*Bs)[BN][BKP] = (uint32_t(*)[BN][BKP])(sm + 2 * BM * BKP);

    int z = blockIdx.z, zb = z / ZH, zh = z % ZH;
    A += (size_t)zb * aob + (size_t)zh * aoh;
    B += (size_t)zb * bob + (size_t)zh * boh;
    C += (size_t)zb * cob + (size_t)zh * coh;

    int m0, n0;
    if (TRI) {
        int id = blockIdx.x;
        int ti = (int)((sqrtf(8.0f * id + 1.0f) - 1.0f) * 0.5f);
        while ((ti + 1) * (ti + 2) / 2 <= id) ti++;
        while (ti * (ti + 1) / 2 > id) ti--;
        int tj = id - ti * (ti + 1) / 2;
        m0 = ti * BM; n0 = tj * BN;
    } else {
        m0 = blockIdx.y * BM; n0 = blockIdx.x * BN;
    }

    int tid = threadIdx.x;
    int warp = tid >> 5, lane = tid & 31;
    int wm0 = (warp >> 2) * 64;
    int wn0 = (warp & 3) * 32;
    int r = lane >> 2, cq = lane & 3;

    int lrow = tid >> 3;          // staging row 0..31 per pass
    int lcol = (tid & 7) * 4;     // staging col (floats)

    float acc[4][4][4] = {};
    float4 ra[4], rb[4];

    // prologue: load k-tile 0, fill buffer 0
    #pragma unroll
    for (int p = 0; p < 4; p++) {
        ra[p] = *(const float4*)(A + (size_t)(m0 + p * 32 + lrow) * lda + lcol);
        rb[p] = *(const float4*)(B + (size_t)(n0 + p * 32 + lrow) * ldb + lcol);
    }
    #pragma unroll
    for (int p = 0; p < 4; p++) {
        uint32_t* as = &As[0][p * 32 + lrow][lcol];
        as[0] = f2tf(ra[p].x); as[1] = f2tf(ra[p].y); as[2] = f2tf(ra[p].z); as[3] = f2tf(ra[p].w);
        uint32_t* bs = &Bs[0][p * 32 + lrow][lcol];
        bs[0] = f2tf(rb[p].x); bs[1] = f2tf(rb[p].y); bs[2] = f2tf(rb[p].z); bs[3] = f2tf(rb[p].w);
    }
    __syncthreads();

    int KT = K / BK;
    for (int kt = 0; kt < KT; kt++) {
        int cur = kt & 1, nxt = cur ^ 1;
        if (kt + 1 < KT) {
            int kc = (kt + 1) * BK;
            #pragma unroll
            for (int p = 0; p < 4; p++) {
                ra[p] = *(const float4*)(A + (size_t)(m0 + p * 32 + lrow) * lda + kc + lcol);
                rb[p] = *(const float4*)(B + (size_t)(n0 + p * 32 + lrow) * ldb + kc + lcol);
            }
        }
        #pragma unroll
        for (int ks = 0; ks < 32; ks += 8) {
            uint32_t a[4][4], b[4][2];
            #pragma unroll
            for (int mf = 0; mf < 4; mf++) {
                int row = wm0 + mf * 16 + r;
                a[mf][0] = As[cur][row][ks + cq];
                a[mf][1] = As[cur][row + 8][ks + cq];
                a[mf][2] = As[cur][row][ks + cq + 4];
                a[mf][3] = As[cur][row + 8][ks + cq + 4];
            }
            #pragma unroll
            for (int nf = 0; nf < 4; nf++) {
                int col = wn0 + nf * 8 + r;
                b[nf][0] = Bs[cur][col][ks + cq];
                b[nf][1] = Bs[cur][col][ks + cq + 4];
            }
            #pragma unroll
            for (int mf = 0; mf < 4; mf++)
                #pragma unroll
                for (int nf = 0; nf < 4; nf++)
                    mma_tf32(acc[mf][nf], a[mf], b[nf]);
        }
        if (kt + 1 < KT) {
            #pragma unroll
            for (int p = 0; p < 4; p++) {
                uint32_t* as = &As[nxt][p * 32 + lrow][lcol];
                as[0] = f2tf(ra[p].x); as[1] = f2tf(ra[p].y); as[2] = f2tf(ra[p].z); as[3] = f2tf(ra[p].w);
                uint32_t* bs = &Bs[nxt][p * 32 + lrow][lcol];
                bs[0] = f2tf(rb[p].x); bs[1] = f2tf(rb[p].y); bs[2] = f2tf(rb[p].z); bs[3] = f2tf(rb[p].w);
            }
            __syncthreads();
        }
    }

    // epilogue
    #pragma unroll
    for (int mf = 0; mf < 4; mf++) {
        #pragma unroll
        for (int nf = 0; nf < 4; nf++) {
            int m = m0 + wm0 + mf * 16 + r;
            int n = n0 + wn0 + nf * 8 + cq * 2;
            float v0 = acc[mf][nf][0] * scale;
            float v1 = acc[mf][nf][1] * scale;
            float v2 = acc[mf][nf][2] * scale;
            float v3 = acc[mf][nf][3] * scale;
            if (bias) { float b0 = bias[n], b1 = bias[n + 1]; v0 += b0; v1 += b1; v2 += b0; v3 += b1; }
            if (relu) { v0 = fmaxf(v0, 0.f); v1 = fmaxf(v1, 0.f); v2 = fmaxf(v2, 0.f); v3 = fmaxf(v3, 0.f); }
            *(float2*)&C[(size_t)m * ldc + n] = make_float2(v0, v1);
            *(float2*)&C[(size_t)(m + 8) * ldc + n] = make_float2(v2, v3);
        }
    }
}

// ============================================================================
// NN tensor GEMM for AV: C[M,N] = A[M,K] @ B[K,N] (B row-major, transposed in
// smem). BM=128, BN=64, BK=32, 256 threads (8 warps, 4m x 2n), warp 32x32.
// Causal k-limit: weights are zero for k >= m0+BM (softmax wrote exact zeros).
// ============================================================================
__global__ void __launch_bounds__(256)
tgemm_nn_av(const float* __restrict__ A, int lda,
            const float* __restrict__ B, int ldb,
            float* __restrict__ C, int ldc,
            int K, int ZH,
            long long aob, long long aoh,
            long long bob, long long boh,
            long long cob, long long coh)
{
    const int BM = 128, BN = 64, BK = 32;
    extern __shared__ uint32_t sm[];
    uint32_t (*As)[BM][BKP] = (uint32_t(*)[BM][BKP])sm;
    uint32_t (*Bs)[BN][BKP] = (uint32_t(*)[BN][BKP])(sm + 2 * BM * BKP);

    int z = blockIdx.z, zb = z / ZH, zh = z % ZH;
    A += (size_t)zb * aob + (size_t)zh * aoh;
    B += (size_t)zb * bob + (size_t)zh * boh;
    C += (size_t)zb * cob + (size_t)zh * coh;

    int m0 = blockIdx.y * BM;
    int n0 = blockIdx.x * BN;
    int Keff = min(K, m0 + BM);      // causal: later keys have zero weight

    int tid = threadIdx.x;
    int warp = tid >> 5, lane = tid & 31;
    int wm0 = (warp >> 1) * 32;
    int wn0 = (warp & 1) * 32;
    int r = lane >> 2, cq = lane & 3;

    int lrow = tid >> 3;          // A staging
    int lcol = (tid & 7) * 4;
    int bkrow0 = tid >> 4;        // B staging: k row (0..15 per pass)
    int bnc = (tid & 15) * 4;     // B staging: n col

    float acc[2][4][4] = {};
    float4 ra[4], rb[2];

    #pragma unroll
    for (int p = 0; p < 4; p++)
        ra[p] = *(const float4*)(A + (size_t)(m0 + p * 32 + lrow) * lda + lcol);
    #pragma unroll
    for (int p = 0; p < 2; p++)
        rb[p] = *(const float4*)(B + (size_t)(p * 16 + bkrow0) * ldb + n0 + bnc);
    #pragma unroll
    for (int p = 0; p < 4; p++) {
        uint32_t* as = &As[0][p * 32 + lrow][lcol];
        as[0] = f2tf(ra[p].x); as[1] = f2tf(ra[p].y); as[2] = f2tf(ra[p].z); as[3] = f2tf(ra[p].w);
    }
    #pragma unroll
    for (int p = 0; p < 2; p++) {
        int kr = p * 16 + bkrow0;
        Bs[0][bnc + 0][kr] = f2tf(rb[p].x);
        Bs[0][bnc + 1][kr] = f2tf(rb[p].y);
        Bs[0][bnc + 2][kr] = f2tf(rb[p].z);
        Bs[0][bnc + 3][kr] = f2tf(rb[p].w);
    }
    __syncthreads();

    int KT = Keff / BK;
    for (int kt = 0; kt < KT; kt++) {
        int cur = kt & 1, nxt = cur ^ 1;
        if (kt + 1 < KT) {
            int kc = (kt + 1) * BK;
            #pragma unroll
            for (int p = 0; p < 4; p++)
                ra[p] = *(const float4*)(A + (size_t)(m0 + p * 32 + lrow) * lda + kc + lcol);
            #pragma unroll
            for (int p = 0; p < 2; p++)
                rb[p] = *(const float4*)(B + (size_t)(kc + p * 16 + bkrow0) * ldb + n0 + bnc);
        }
        #pragma unroll
        for (int ks = 0; ks < 32; ks += 8) {
            uint32_t a[2][4], b[4][2];
            #pragma unroll
            for (int mf = 0; mf < 2; mf++) {
                int row = wm0 + mf * 16 + r;
                a[mf][0] = As[cur][row][ks + cq];
                a[mf][1] = As[cur][row + 8][ks + cq];
                a[mf][2] = As[cur][row][ks + cq + 4];
                a[mf][3] = As[cur][row + 8][ks + cq + 4];
            }
            #pragma unroll
            for (int nf = 0; nf < 4; nf++) {
                int col = wn0 + nf * 8 + r;
                b[nf][0] = Bs[cur][col][ks + cq];
                b[nf][1] = Bs[cur][col][ks + cq + 4];
            }
            #pragma unroll
            for (int mf = 0; mf < 2; mf++)
                #pragma unroll
                for (int nf = 0; nf < 4; nf++)
                    mma_tf32(acc[mf][nf], a[mf], b[nf]);
        }
        if (kt + 1 < KT) {
            #pragma unroll
            for (int p = 0; p < 4; p++) {
                uint32_t* as = &As[nxt][p * 32 + lrow][lcol];
                as[0] = f2tf(ra[p].x); as[1] = f2tf(ra[p].y); as[2] = f2tf(ra[p].z); as[3] = f2tf(ra[p].w);
            }
            #pragma unroll
            for (int p = 0; p < 2; p++) {
                int kr = p * 16 + bkrow0;
                Bs[nxt][bnc + 0][kr] = f2tf(rb[p].x);
                Bs[nxt][bnc + 1][kr] = f2tf(rb[p].y);
                Bs[nxt][bnc + 2][kr] = f2tf(rb[p].z);
                Bs[nxt][bnc + 3][kr] = f2tf(rb[p].w);
            }
            __syncthreads();
        }
    }

    #pragma unroll
    for (int mf = 0; mf < 2; mf++) {
        #pragma unroll
        for (int nf = 0; nf < 4; nf++) {
            int m = m0 + wm0 + mf * 16 + r;
            int n = n0 + wn0 + nf * 8 + cq * 2;
            *(float2*)&C[(size_t)m * ldc + n] = make_float2(acc[mf][nf][0], acc[mf][nf][1]);
            *(float2*)&C[(size_t)(m + 8) * ldc + n] = make_float2(acc[mf][nf][2], acc[mf][nf][3]);
        }
    }
}

// ---------------- masked softmax over rows of length L --------------------
__global__ void __launch_bounds__(256)
softmax_kernel(float* __restrict__ w, const int* __restrict__ seq_lens)
{
    __shared__ float red[256];
    int row = blockIdx.x;
    int l = row % LL;
    int b = row / (HH * LL);
    float* p = w + (size_t)row * LL;
    int sl = seq_lens[b];
    int tid = threadIdx.x;

    float v[4];
    float mx = -3.4e38f;
    #pragma unroll
    for (int i = 0; i < 4; i++) {
        int m = tid + i * 256;
        float x = (m < sl && m < l) ? p[m] : NINF;   // skip loading masked region
        v[i] = x;
        mx = fmaxf(mx, x);
    }
    red[tid] = mx; __syncthreads();
    for (int o = 128; o > 0; o >>= 1) {
        if (tid < o) red[tid] = fmaxf(red[tid], red[tid + o]);
        __syncthreads();
    }
    mx = red[0];
    __syncthreads();

    float sum = 0.0f;
    #pragma unroll
    for (int i = 0; i < 4; i++) { v[i] = __expf(v[i] - mx); sum += v[i]; }
    red[tid] = sum; __syncthreads();
    for (int o = 128; o > 0; o >>= 1) {
        if (tid < o) red[tid] += red[tid + o];
        __syncthreads();
    }
    float inv = 1.0f / red[0];
    #pragma unroll
    for (int i = 0; i < 4; i++) p[tid + i * 256] = v[i] * inv;
}

// ---------------- residual + LayerNorm -------------------------------------
__global__ void __launch_bounds__(128)
ln_kernel(const float* __restrict__ x, const float* __restrict__ r,
          const float* __restrict__ g, const float* __restrict__ be,
          float* __restrict__ out, int zero_l0)
{
    __shared__ float red[128];
    int row = blockIdx.x;
    int l = row % LL;
    const float* xp = x + (size_t)row * DM;
    const float* rp = r + (size_t)row * DM;
    int tid = threadIdx.x;
    bool skip = (zero_l0 && l == 0);

    float v[4];
    float s = 0.0f;
    #pragma unroll
    for (int i = 0; i < 4; i++) {
        int c = tid + i * 128;
        v[i] = xp[c] + (skip ? 0.0f : rp[c]);
        s += v[i];
    }
    red[tid] = s; __syncthreads();
    for (int o = 64; o > 0; o >>= 1) {
        if (tid < o) red[tid] += red[tid + o];
        __syncthreads();
    }
    float mu = red[0] * (1.0f / DM);
    __syncthreads();

    float vs = 0.0f;
    #pragma unroll
    for (int i = 0; i < 4; i++) { float d = v[i] - mu; vs += d * d; }
    red[tid] = vs; __syncthreads();
    for (int o = 64; o > 0; o >>= 1) {
        if (tid < o) red[tid] += red[tid + o];
        __syncthreads();
    }
    float inv = rsqrtf(red[0] * (1.0f / DM) + 1e-5f);
    #pragma unroll
    for (int i = 0; i < 4; i++) {
        int c = tid + i * 128;
        out[(size_t)row * DM + c] = (v[i] - mu) * inv * g[c] + be[c];
    }
}

// ---------------- positional encoding add ---------------------------------
__global__ void __launch_bounds__(256)
add_pos_kernel(float* __restrict__ x, const float* __restrict__ times)
{
    int idx = blockIdx.x * blockDim.x + threadIdx.x;
    if (idx >= MROWS * DM) return;
    int j = idx % DM;
    int row = idx / DM;
    float t = times[row];
    int jj = (j < DM / 2) ? j : j - DM / 2;
    float d = (float)jj / (float)(DM / 2 - 1);
    float denum = powf(10000.0f, d);
    float arg = t / denum;
    x[idx] += (j < DM / 2) ? sinf(arg) : cosf(arg);
}

// ---------------- host-side orchestration ----------------------------------
extern "C" void kernel_launch(void* const* d_in, const int* in_sizes, int n_in,
                              void* d_out, int out_size)
{
    const float* emb   = (const float*)d_in[0];
    const float* times = (const float*)d_in[1];
    const int*   seq   = (const int*)  d_in[2];
    const float* Wp    = (const float*)d_in[3];
    const float* bp    = (const float*)d_in[4];
    const float* Win   = (const float*)d_in[5];
    const float* bin_  = (const float*)d_in[6];
    const float* Wout  = (const float*)d_in[7];
    const float* bout  = (const float*)d_in[8];
    const float* g1    = (const float*)d_in[9];
    const float* be1   = (const float*)d_in[10];
    const float* W1    = (const float*)d_in[11];
    const float* b1    = (const float*)d_in[12];
    const float* W2    = (const float*)d_in[13];
    const float* b2    = (const float*)d_in[14];
    const float* g2    = (const float*)d_in[15];
    const float* be2   = (const float*)d_in[16];

    float *x, *proj, *scores, *sa, *tmp, *ff;
    cudaGetSymbolAddress((void**)&x,      g_x);
    cudaGetSymbolAddress((void**)&proj,   g_proj);
    cudaGetSymbolAddress((void**)&scores, g_scores);
    cudaGetSymbolAddress((void**)&sa,     g_sa);
    cudaGetSymbolAddress((void**)&tmp,    g_tmp);
    cudaGetSymbolAddress((void**)&ff,     g_ff);

    const int SMEM_TN = (2 * 128 * BKP + 2 * 128 * BKP) * 4;   // 73728
    const int SMEM_NN = (2 * 128 * BKP + 2 * 64 * BKP) * 4;    // 55296
    cudaFuncSetAttribute(tgemm_tn<0>, cudaFuncAttributeMaxDynamicSharedMemorySize, SMEM_TN);
    cudaFuncSetAttribute(tgemm_tn<1>, cudaFuncAttributeMaxDynamicSharedMemorySize, SMEM_TN);
    cudaFuncSetAttribute(tgemm_nn_av, cudaFuncAttributeMaxDynamicSharedMemorySize, SMEM_NN);

    const float inv_sqrt_d = 1.0f / sqrtf((float)DM);

    // x = emb @ Wp^T + bp
    tgemm_tn<0><<<dim3(DM / 128, MROWS / 128, 1), 256, SMEM_TN>>>(
        emb, DIN, Wp, DIN, x, DM, bp, DIN, 1.0f, 0, 1, 0, 0, 0, 0, 0, 0);
    add_pos_kernel<<<(MROWS * DM + 255) / 256, 256>>>(x, times);

    for (int i = 0; i < NLAY; i++) {
        const float* Wi   = Win  + (size_t)i * DINP * DM;
        const float* bini = bin_ + (size_t)i * DINP;
        const float* Woi  = Wout + (size_t)i * DM * (HH * DV);
        const float* boi  = bout + (size_t)i * DM;
        const float* g1i  = g1   + (size_t)i * DM;
        const float* be1i = be1  + (size_t)i * DM;
        const float* W1i  = W1   + (size_t)i * DFF * DM;
        const float* b1i  = b1   + (size_t)i * DFF;
        const float* W2i  = W2   + (size_t)i * DM * DFF;
        const float* b2i  = b2   + (size_t)i * DM;
        const float* g2i  = g2   + (size_t)i * DM;
        const float* be2i = be2  + (size_t)i * DM;

        // proj = x @ Win^T + bin   (4096 x 8704, K=512)
        tgemm_tn<0><<<dim3(DINP / 128, MROWS / 128, 1), 256, SMEM_TN>>>(
            x, DM, Wi, DM, proj, DINP, bini, DM, 1.0f, 0, 1, 0, 0, 0, 0, 0, 0);

        // scores: only lower-triangular tiles (36 of 64), per (b,h)
        tgemm_tn<1><<<dim3(36, 1, BB * HH), 256, SMEM_TN>>>(
            proj, DINP, proj + HH * DM, DINP, scores, LL, nullptr,
            DM, inv_sqrt_d, 0, HH,
            (long long)LL * DINP, (long long)DM,
            (long long)LL * DINP, (long long)DM,
            (long long)HH * LL * LL, (long long)LL * LL);

        // masked softmax (sanitizes skipped tiles: writes exact zeros there)
        softmax_kernel<<<BB * HH * LL, 256>>>(scores, seq);

        // sa = softmax(w) @ v  (K limited to m0+128 by causality)
        tgemm_nn_av<<<dim3(1, LL / 128, BB * HH), 256, SMEM_NN>>>(
            scores, LL, proj + 2 * HH * DM, DINP, sa, HH * DV, LL, HH,
            (long long)HH * LL * LL, (long long)LL * LL,
            (long long)LL * DINP, (long long)DV,
            (long long)LL * (HH * DV), (long long)DV);

        // tmp = sa @ Wout^T + bout
        tgemm_tn<0><<<dim3(DM / 128, MROWS / 128, 1), 256, SMEM_TN>>>(
            sa, HH * DV, Woi, HH * DV, tmp, DM, boi, HH * DV, 1.0f, 0, 1,
            0, 0, 0, 0, 0, 0);

        ln_kernel<<<MROWS, 128>>>(x, tmp, g1i, be1i, x, 1);

        // ff = relu(x @ W1^T + b1)
        tgemm_tn<0><<<dim3(DFF / 128, MROWS / 128, 1), 256, SMEM_TN>>>(
            x, DM, W1i, DM, ff, DFF, b1i, DM, 1.0f, 1, 1, 0, 0, 0, 0, 0, 0);

        // tmp = ff @ W2^T + b2
        tgemm_tn<0><<<dim3(DM / 128, MROWS / 128, 1), 256, SMEM_TN>>>(
            ff, DFF, W2i, DFF, tmp, DM, b2i, DFF, 1.0f, 0, 1, 0, 0, 0, 0, 0, 0);

        float* dst = (i == NLAY - 1) ? (float*)d_out : x;
        ln_kernel<<<MROWS, 128>>>(x, tmp, g2i, be2i, dst, 0);
    }
}

// round 4
// speedup vs baseline: 4.9081x; 1.2772x over previous
#include <cuda_runtime.h>
#include <math.h>
#include <stdint.h>

// ---------------- problem constants ----------------
#define BB   4
#define LL   1024
#define DIN  256
#define DM   512
#define HH   8
#define DV   64
#define DFF  2048
#define NLAY 2
#define DINP (2*HH*DM + HH*DV)   // 8704
#define MROWS (BB*LL)            // 4096
#define NINF (-1.0e6f)

#define BKP 36   // padded k stride for the (unchanged) AV kernel

// ---------------- scratch ----------------
__device__ float g_x[MROWS * DM];
__device__ float g_proj[MROWS * DINP];
__device__ float g_scores[BB * HH * LL * LL];
__device__ float g_sa[MROWS * (HH*DV)];
__device__ float g_tmp[MROWS * DM];
__device__ float g_ff[MROWS * DFF];

// ---------------- helpers ----------------
__device__ __forceinline__ uint32_t f2tf(float f) {
    uint32_t r; asm("cvt.rna.tf32.f32 %0, %1;" : "=r"(r) : "f"(f)); return r;
}
__device__ __forceinline__ void cvt_inplace(uint32_t& x) {
    asm("cvt.rna.tf32.f32 %0, %0;" : "+r"(x));
}
__device__ __forceinline__ void mma_tf32(float* c, const uint32_t* a, const uint32_t* b) {
    asm volatile("mma.sync.aligned.m16n8k8.row.col.f32.tf32.tf32.f32 "
        "{%0,%1,%2,%3}, {%4,%5,%6,%7}, {%8,%9}, {%0,%1,%2,%3};"
        : "+f"(c[0]), "+f"(c[1]), "+f"(c[2]), "+f"(c[3])
        : "r"(a[0]), "r"(a[1]), "r"(a[2]), "r"(a[3]), "r"(b[0]), "r"(b[1]));
}
__device__ __forceinline__ void ldsm4(uint32_t& r0, uint32_t& r1, uint32_t& r2, uint32_t& r3,
                                      uint32_t addr) {
    asm volatile("ldmatrix.sync.aligned.m8n8.x4.shared.b16 {%0,%1,%2,%3}, [%4];"
        : "=r"(r0), "=r"(r1), "=r"(r2), "=r"(r3) : "r"(addr));
}
__device__ __forceinline__ void cpasync16(uint32_t dst, const void* src) {
    asm volatile("cp.async.cg.shared.global [%0], [%1], 16;" :: "r"(dst), "l"(src));
}
__device__ __forceinline__ void cp_commit() {
    asm volatile("cp.async.commit_group;");
}
template<int N>
__device__ __forceinline__ void cp_wait() {
    asm volatile("cp.async.wait_group %0;" :: "n"(N));
}

// ============================================================================
// TN tensor GEMM: C[M,N] = scale*(A[M,K] @ B[N,K]^T) + bias, optional relu.
// BM=BN=128, BK=32, 256 threads (8 warps, 2m x 4n), warp tile 64x32.
// cp.async 3-stage pipeline, XOR-swizzled smem, ldmatrix.x4 fragment loads.
// TRI=1: lower-triangular 128x128 tile set for strictly-causal scores.
// ============================================================================
#define STAGES 3
#define TILE_WORDS (128 * 32)           // floats per operand tile
#define TILE_BYTES (TILE_WORDS * 4)     // 16 KB

template<int TRI>
__global__ void __launch_bounds__(256, 2)
tgemm_tn(const float* __restrict__ A, int lda,
         const float* __restrict__ B, int ldb,
         float* __restrict__ C, int ldc,
         const float* __restrict__ bias,
         int K, float scale, int relu, int ZH,
         long long aob, long long aoh,
         long long bob, long long boh,
         long long cob, long long coh)
{
    extern __shared__ float sm[];
    const uint32_t sbase = (uint32_t)__cvta_generic_to_shared(sm);
    const uint32_t aS = sbase;
    const uint32_t bS = sbase + STAGES * TILE_BYTES;

    int z = blockIdx.z, zb = z / ZH, zh = z % ZH;
    A += (size_t)zb * aob + (size_t)zh * aoh;
    B += (size_t)zb * bob + (size_t)zh * boh;
    C += (size_t)zb * cob + (size_t)zh * coh;

    int m0, n0;
    if (TRI) {
        int id = blockIdx.x;
        int ti = (int)((sqrtf(8.0f * id + 1.0f) - 1.0f) * 0.5f);
        while ((ti + 1) * (ti + 2) / 2 <= id) ti++;
        while (ti * (ti + 1) / 2 > id) ti--;
        int tj = id - ti * (ti + 1) / 2;
        m0 = ti * 128; n0 = tj * 128;
    } else {
        m0 = blockIdx.y * 128; n0 = blockIdx.x * 128;
    }

    int tid = threadIdx.x;
    int warp = tid >> 5, lane = tid & 31;
    int wm0 = (warp >> 2) * 64;
    int wn0 = (warp & 3) * 32;
    int r = lane >> 2, cq = lane & 3;

    // cp.async staging: thread covers rows lr, lr+32, lr+64, lr+96, chunk lc
    int lr = tid >> 3;
    int lc = tid & 7;

    // ldmatrix lane geometry
    int grp = lane >> 3;       // 0..3 (matrix index within .x4)
    int j8  = lane & 7;        // row within 8x8 matrix
    int a_row_base = wm0 + ((grp & 1) << 3) + j8;   // + mf*16
    int a_cbit = grp >> 1;
    int b_col_base = wn0 + ((grp >> 1) << 3) + j8;  // + nfpair*16
    int b_cbit = grp & 1;

    float acc[4][4][4] = {};

    int KT = K / 32;

    // ---- stage loader ----
    auto load_stage = [&](int s, int kc) {
        uint32_t as = aS + s * TILE_BYTES;
        uint32_t bs = bS + s * TILE_BYTES;
        #pragma unroll
        for (int p = 0; p < 4; p++) {
            int row = lr + p * 32;
            int ch = lc ^ (row & 7);
            cpasync16(as + (row * 8 + ch) * 16,
                      A + (size_t)(m0 + row) * lda + kc + lc * 4);
            cpasync16(bs + (row * 8 + ch) * 16,
                      B + (size_t)(n0 + row) * ldb + kc + lc * 4);
        }
    };

    // prologue: prime stages 0 and 1
    load_stage(0, 0);
    cp_commit();
    if (KT > 1) load_stage(1, 32);
    cp_commit();

    for (int kt = 0; kt < KT; kt++) {
        cp_wait<1>();
        __syncthreads();

        // issue next stage (overwrites the stage consumed 2 iterations ago)
        if (kt + 2 < KT) load_stage((kt + 2) % STAGES, (kt + 2) * 32);
        cp_commit();

        uint32_t aSb = aS + (kt % STAGES) * TILE_BYTES;
        uint32_t bSb = bS + (kt % STAGES) * TILE_BYTES;

        #pragma unroll
        for (int step = 0; step < 4; step++) {
            int kb = step * 2;
            uint32_t a[4][4], b[4][2];
            #pragma unroll
            for (int mf = 0; mf < 4; mf++) {
                int row = a_row_base + mf * 16;
                uint32_t addr = aSb + (row * 8 + ((kb + a_cbit) ^ (row & 7))) * 16;
                ldsm4(a[mf][0], a[mf][1], a[mf][2], a[mf][3], addr);
            }
            #pragma unroll
            for (int np = 0; np < 2; np++) {
                int col = b_col_base + np * 16;
                uint32_t addr = bSb + (col * 8 + ((kb + b_cbit) ^ (col & 7))) * 16;
                ldsm4(b[np*2][0], b[np*2][1], b[np*2+1][0], b[np*2+1][1], addr);
            }
            #pragma unroll
            for (int mf = 0; mf < 4; mf++)
                #pragma unroll
                for (int q = 0; q < 4; q++) cvt_inplace(a[mf][q]);
            #pragma unroll
            for (int nf = 0; nf < 4; nf++) {
                cvt_inplace(b[nf][0]); cvt_inplace(b[nf][1]);
            }
            #pragma unroll
            for (int mf = 0; mf < 4; mf++)
                #pragma unroll
                for (int nf = 0; nf < 4; nf++)
                    mma_tf32(acc[mf][nf], a[mf], b[nf]);
        }
        __syncthreads();
    }

    // epilogue
    #pragma unroll
    for (int mf = 0; mf < 4; mf++) {
        #pragma unroll
        for (int nf = 0; nf < 4; nf++) {
            int m = m0 + wm0 + mf * 16 + r;
            int n = n0 + wn0 + nf * 8 + cq * 2;
            float v0 = acc[mf][nf][0] * scale;
            float v1 = acc[mf][nf][1] * scale;
            float v2 = acc[mf][nf][2] * scale;
            float v3 = acc[mf][nf][3] * scale;
            if (bias) { float b0 = bias[n], b1 = bias[n + 1]; v0 += b0; v1 += b1; v2 += b0; v3 += b1; }
            if (relu) { v0 = fmaxf(v0, 0.f); v1 = fmaxf(v1, 0.f); v2 = fmaxf(v2, 0.f); v3 = fmaxf(v3, 0.f); }
            *(float2*)&C[(size_t)m * ldc + n] = make_float2(v0, v1);
            *(float2*)&C[(size_t)(m + 8) * ldc + n] = make_float2(v2, v3);
        }
    }
}

// ============================================================================
// NN tensor GEMM for AV (unchanged from round 3): C = A @ B, causal k-limit.
// ============================================================================
__global__ void __launch_bounds__(256)
tgemm_nn_av(const float* __restrict__ A, int lda,
            const float* __restrict__ B, int ldb,
            float* __restrict__ C, int ldc,
            int K, int ZH,
            long long aob, long long aoh,
            long long bob, long long boh,
            long long cob, long long coh)
{
    const int BM = 128, BN = 64;
    extern __shared__ uint32_t smu[];
    uint32_t (*As)[BM][BKP] = (uint32_t(*)[BM][BKP])smu;
    uint32_t (*Bs)[BN][BKP] = (uint32_t(*)[BN][BKP])(smu + 2 * BM * BKP);

    int z = blockIdx.z, zb = z / ZH, zh = z % ZH;
    A += (size_t)zb * aob + (size_t)zh * aoh;
    B += (size_t)zb * bob + (size_t)zh * boh;
    C += (size_t)zb * cob + (size_t)zh * coh;

    int m0 = blockIdx.y * BM;
    int n0 = blockIdx.x * BN;
    int Keff = min(K, m0 + BM);

    int tid = threadIdx.x;
    int warp = tid >> 5, lane = tid & 31;
    int wm0 = (warp >> 1) * 32;
    int wn0 = (warp & 1) * 32;
    int r = lane >> 2, cq = lane & 3;

    int lrow = tid >> 3;
    int lcol = (tid & 7) * 4;
    int bkrow0 = tid >> 4;
    int bnc = (tid & 15) * 4;

    float acc[2][4][4] = {};
    float4 ra[4], rb[2];

    #pragma unroll
    for (int p = 0; p < 4; p++)
        ra[p] = *(const float4*)(A + (size_t)(m0 + p * 32 + lrow) * lda + lcol);
    #pragma unroll
    for (int p = 0; p < 2; p++)
        rb[p] = *(const float4*)(B + (size_t)(p * 16 + bkrow0) * ldb + n0 + bnc);
    #pragma unroll
    for (int p = 0; p < 4; p++) {
        uint32_t* as = &As[0][p * 32 + lrow][lcol];
        as[0] = f2tf(ra[p].x); as[1] = f2tf(ra[p].y); as[2] = f2tf(ra[p].z); as[3] = f2tf(ra[p].w);
    }
    #pragma unroll
    for (int p = 0; p < 2; p++) {
        int kr = p * 16 + bkrow0;
        Bs[0][bnc + 0][kr] = f2tf(rb[p].x);
        Bs[0][bnc + 1][kr] = f2tf(rb[p].y);
        Bs[0][bnc + 2][kr] = f2tf(rb[p].z);
        Bs[0][bnc + 3][kr] = f2tf(rb[p].w);
    }
    __syncthreads();

    int KT = Keff / 32;
    for (int kt = 0; kt < KT; kt++) {
        int cur = kt & 1, nxt = cur ^ 1;
        if (kt + 1 < KT) {
            int kc = (kt + 1) * 32;
            #pragma unroll
            for (int p = 0; p < 4; p++)
                ra[p] = *(const float4*)(A + (size_t)(m0 + p * 32 + lrow) * lda + kc + lcol);
            #pragma unroll
            for (int p = 0; p < 2; p++)
                rb[p] = *(const float4*)(B + (size_t)(kc + p * 16 + bkrow0) * ldb + n0 + bnc);
        }
        #pragma unroll
        for (int ks = 0; ks < 32; ks += 8) {
            uint32_t a[2][4], b[4][2];
            #pragma unroll
            for (int mf = 0; mf < 2; mf++) {
                int row = wm0 + mf * 16 + r;
                a[mf][0] = As[cur][row][ks + cq];
                a[mf][1] = As[cur][row + 8][ks + cq];
                a[mf][2] = As[cur][row][ks + cq + 4];
                a[mf][3] = As[cur][row + 8][ks + cq + 4];
            }
            #pragma unroll
            for (int nf = 0; nf < 4; nf++) {
                int col = wn0 + nf * 8 + r;
                b[nf][0] = Bs[cur][col][ks + cq];
                b[nf][1] = Bs[cur][col][ks + cq + 4];
            }
            #pragma unroll
            for (int mf = 0; mf < 2; mf++)
                #pragma unroll
                for (int nf = 0; nf < 4; nf++)
                    mma_tf32(acc[mf][nf], a[mf], b[nf]);
        }
        if (kt + 1 < KT) {
            #pragma unroll
            for (int p = 0; p < 4; p++) {
                uint32_t* as = &As[nxt][p * 32 + lrow][lcol];
                as[0] = f2tf(ra[p].x); as[1] = f2tf(ra[p].y); as[2] = f2tf(ra[p].z); as[3] = f2tf(ra[p].w);
            }
            #pragma unroll
            for (int p = 0; p < 2; p++) {
                int kr = p * 16 + bkrow0;
                Bs[nxt][bnc + 0][kr] = f2tf(rb[p].x);
                Bs[nxt][bnc + 1][kr] = f2tf(rb[p].y);
                Bs[nxt][bnc + 2][kr] = f2tf(rb[p].z);
                Bs[nxt][bnc + 3][kr] = f2tf(rb[p].w);
            }
            __syncthreads();
        }
    }

    #pragma unroll
    for (int mf = 0; mf < 2; mf++) {
        #pragma unroll
        for (int nf = 0; nf < 4; nf++) {
            int m = m0 + wm0 + mf * 16 + r;
            int n = n0 + wn0 + nf * 8 + cq * 2;
            *(float2*)&C[(size_t)m * ldc + n] = make_float2(acc[mf][nf][0], acc[mf][nf][1]);
            *(float2*)&C[(size_t)(m + 8) * ldc + n] = make_float2(acc[mf][nf][2], acc[mf][nf][3]);
        }
    }
}

// ---------------- masked softmax ----------------
__global__ void __launch_bounds__(256)
softmax_kernel(float* __restrict__ w, const int* __restrict__ seq_lens)
{
    __shared__ float red[256];
    int row = blockIdx.x;
    int l = row % LL;
    int b = row / (HH * LL);
    float* p = w + (size_t)row * LL;
    int sl = seq_lens[b];
    int tid = threadIdx.x;

    float v[4];
    float mx = -3.4e38f;
    #pragma unroll
    for (int i = 0; i < 4; i++) {
        int m = tid + i * 256;
        float x = (m < sl && m < l) ? p[m] : NINF;
        v[i] = x;
        mx = fmaxf(mx, x);
    }
    red[tid] = mx; __syncthreads();
    for (int o = 128; o > 0; o >>= 1) {
        if (tid < o) red[tid] = fmaxf(red[tid], red[tid + o]);
        __syncthreads();
    }
    mx = red[0];
    __syncthreads();

    float sum = 0.0f;
    #pragma unroll
    for (int i = 0; i < 4; i++) { v[i] = __expf(v[i] - mx); sum += v[i]; }
    red[tid] = sum; __syncthreads();
    for (int o = 128; o > 0; o >>= 1) {
        if (tid < o) red[tid] += red[tid + o];
        __syncthreads();
    }
    float inv = 1.0f / red[0];
    #pragma unroll
    for (int i = 0; i < 4; i++) p[tid + i * 256] = v[i] * inv;
}

// ---------------- residual + LayerNorm ----------------
__global__ void __launch_bounds__(128)
ln_kernel(const float* __restrict__ x, const float* __restrict__ r,
          const float* __restrict__ g, const float* __restrict__ be,
          float* __restrict__ out, int zero_l0)
{
    __shared__ float red[128];
    int row = blockIdx.x;
    int l = row % LL;
    const float* xp = x + (size_t)row * DM;
    const float* rp = r + (size_t)row * DM;
    int tid = threadIdx.x;
    bool skip = (zero_l0 && l == 0);

    float v[4];
    float s = 0.0f;
    #pragma unroll
    for (int i = 0; i < 4; i++) {
        int c = tid + i * 128;
        v[i] = xp[c] + (skip ? 0.0f : rp[c]);
        s += v[i];
    }
    red[tid] = s; __syncthreads();
    for (int o = 64; o > 0; o >>= 1) {
        if (tid < o) red[tid] += red[tid + o];
        __syncthreads();
    }
    float mu = red[0] * (1.0f / DM);
    __syncthreads();

    float vs = 0.0f;
    #pragma unroll
    for (int i = 0; i < 4; i++) { float d = v[i] - mu; vs += d * d; }
    red[tid] = vs; __syncthreads();
    for (int o = 64; o > 0; o >>= 1) {
        if (tid < o) red[tid] += red[tid + o];
        __syncthreads();
    }
    float inv = rsqrtf(red[0] * (1.0f / DM) + 1e-5f);
    #pragma unroll
    for (int i = 0; i < 4; i++) {
        int c = tid + i * 128;
        out[(size_t)row * DM + c] = (v[i] - mu) * inv * g[c] + be[c];
    }
}

// ---------------- positional encoding add ----------------
__global__ void __launch_bounds__(256)
add_pos_kernel(float* __restrict__ x, const float* __restrict__ times)
{
    int idx = blockIdx.x * blockDim.x + threadIdx.x;
    if (idx >= MROWS * DM) return;
    int j = idx % DM;
    int row = idx / DM;
    float t = times[row];
    int jj = (j < DM / 2) ? j : j - DM / 2;
    float d = (float)jj / (float)(DM / 2 - 1);
    float denum = powf(10000.0f, d);
    float arg = t / denum;
    x[idx] += (j < DM / 2) ? sinf(arg) : cosf(arg);
}

// ---------------- host-side orchestration ----------------
extern "C" void kernel_launch(void* const* d_in, const int* in_sizes, int n_in,
                              void* d_out, int out_size)
{
    const float* emb   = (const float*)d_in[0];
    const float* times = (const float*)d_in[1];
    const int*   seq   = (const int*)  d_in[2];
    const float* Wp    = (const float*)d_in[3];
    const float* bp    = (const float*)d_in[4];
    const float* Win   = (const float*)d_in[5];
    const float* bin_  = (const float*)d_in[6];
    const float* Wout  = (const float*)d_in[7];
    const float* bout  = (const float*)d_in[8];
    const float* g1    = (const float*)d_in[9];
    const float* be1   = (const float*)d_in[10];
    const float* W1    = (const float*)d_in[11];
    const float* b1    = (const float*)d_in[12];
    const float* W2    = (const float*)d_in[13];
    const float* b2    = (const float*)d_in[14];
    const float* g2    = (const float*)d_in[15];
    const float* be2   = (const float*)d_in[16];

    float *x, *proj, *scores, *sa, *tmp, *ff;
    cudaGetSymbolAddress((void**)&x,      g_x);
    cudaGetSymbolAddress((void**)&proj,   g_proj);
    cudaGetSymbolAddress((void**)&scores, g_scores);
    cudaGetSymbolAddress((void**)&sa,     g_sa);
    cudaGetSymbolAddress((void**)&tmp,    g_tmp);
    cudaGetSymbolAddress((void**)&ff,     g_ff);

    const int SMEM_TN = STAGES * 2 * TILE_BYTES;              // 98304
    const int SMEM_NN = (2 * 128 * BKP + 2 * 64 * BKP) * 4;   // 55296
    cudaFuncSetAttribute(tgemm_tn<0>, cudaFuncAttributeMaxDynamicSharedMemorySize, SMEM_TN);
    cudaFuncSetAttribute(tgemm_tn<1>, cudaFuncAttributeMaxDynamicSharedMemorySize, SMEM_TN);
    cudaFuncSetAttribute(tgemm_nn_av, cudaFuncAttributeMaxDynamicSharedMemorySize, SMEM_NN);

    const float inv_sqrt_d = 1.0f / sqrtf((float)DM);

    // x = emb @ Wp^T + bp
    tgemm_tn<0><<<dim3(DM / 128, MROWS / 128, 1), 256, SMEM_TN>>>(
        emb, DIN, Wp, DIN, x, DM, bp, DIN, 1.0f, 0, 1, 0, 0, 0, 0, 0, 0);
    add_pos_kernel<<<(MROWS * DM + 255) / 256, 256>>>(x, times);

    for (int i = 0; i < NLAY; i++) {
        const float* Wi   = Win  + (size_t)i * DINP * DM;
        const float* bini = bin_ + (size_t)i * DINP;
        const float* Woi  = Wout + (size_t)i * DM * (HH * DV);
        const float* boi  = bout + (size_t)i * DM;
        const float* g1i  = g1   + (size_t)i * DM;
        const float* be1i = be1  + (size_t)i * DM;
        const float* W1i  = W1   + (size_t)i * DFF * DM;
        const float* b1i  = b1   + (size_t)i * DFF;
        const float* W2i  = W2   + (size_t)i * DM * DFF;
        const float* b2i  = b2   + (size_t)i * DM;
        const float* g2i  = g2   + (size_t)i * DM;
        const float* be2i = be2  + (size_t)i * DM;

        // proj = x @ Win^T + bin   (4096 x 8704, K=512)
        tgemm_tn<0><<<dim3(DINP / 128, MROWS / 128, 1), 256, SMEM_TN>>>(
            x, DM, Wi, DM, proj, DINP, bini, DM, 1.0f, 0, 1, 0, 0, 0, 0, 0, 0);

        // scores: lower-triangular tiles only (36 of 64), per (b,h)
        tgemm_tn<1><<<dim3(36, 1, BB * HH), 256, SMEM_TN>>>(
            proj, DINP, proj + HH * DM, DINP, scores, LL, nullptr,
            DM, inv_sqrt_d, 0, HH,
            (long long)LL * DINP, (long long)DM,
            (long long)LL * DINP, (long long)DM,
            (long long)HH * LL * LL, (long long)LL * LL);

        // masked softmax (writes exact zeros in masked/skipped region)
        softmax_kernel<<<BB * HH * LL, 256>>>(scores, seq);

        // sa = softmax(w) @ v  (K limited to m0+128 by causality)
        tgemm_nn_av<<<dim3(1, LL / 128, BB * HH), 256, SMEM_NN>>>(
            scores, LL, proj + 2 * HH * DM, DINP, sa, HH * DV, LL, HH,
            (long long)HH * LL * LL, (long long)LL * LL,
            (long long)LL * DINP, (long long)DV,
            (long long)LL * (HH * DV), (long long)DV);

        // tmp = sa @ Wout^T + bout
        tgemm_tn<0><<<dim3(DM / 128, MROWS / 128, 1), 256, SMEM_TN>>>(
            sa, HH * DV, Woi, HH * DV, tmp, DM, boi, HH * DV, 1.0f, 0, 1,
            0, 0, 0, 0, 0, 0);

        ln_kernel<<<MROWS, 128>>>(x, tmp, g1i, be1i, x, 1);

        // ff = relu(x @ W1^T + b1)
        tgemm_tn<0><<<dim3(DFF / 128, MROWS / 128, 1), 256, SMEM_TN>>>(
            x, DM, W1i, DM, ff, DFF, b1i, DM, 1.0f, 1, 1, 0, 0, 0, 0, 0, 0);

        // tmp = ff @ W2^T + b2
        tgemm_tn<0><<<dim3(DM / 128, MROWS / 128, 1), 256, SMEM_TN>>>(
            ff, DFF, W2i, DFF, tmp, DM, b2i, DFF, 1.0f, 0, 1, 0, 0, 0, 0, 0, 0);

        float* dst = (i == NLAY - 1) ? (float*)d_out : x;
        ln_kernel<<<MROWS, 128>>>(x, tmp, g2i, be2i, dst, 0);
    }
}